// round 9
// baseline (speedup 1.0000x reference)
#include <cuda_runtime.h>
#include <cuda_fp16.h>
#include <cstdint>
#include <cstddef>

#define BSZ 4
#define SSZ 2048
#define DSZ 4096
#define OSZ 4096
#define ESZ 8
#define RSZ 8
#define MSZ (BSZ*SSZ)            // 8192
#define KLORA (ESZ*RSZ)          // 64
#define KTOT (DSZ+KLORA)         // 4160
#define SCALING 2.0f             // lora_alpha / r = 16/8

// ---------------- scratch (device globals; allocation is forbidden) ----------
__device__ __align__(128) __half g_Ah[(size_t)MSZ*KTOT];   // [x | hw] fp16
__device__ __align__(128) __half g_Bh[(size_t)OSZ*KTOT];   // [W | 2*B_cat] fp16
__device__ float g_xmean[BSZ*DSZ];
__device__ float g_weights[BSZ*ESZ];

// ---------------- PTX helpers (compute_80-era; sm_103 virtual-arch safe) ----
__device__ __forceinline__ uint32_t s2u(const void* p) {
    uint32_t a;
    asm("{ .reg .u64 t; cvta.to.shared.u64 t, %1; cvt.u32.u64 %0, t; }" : "=r"(a) : "l"(p));
    return a;
}
__device__ __forceinline__ void cp16(uint32_t dst, const void* src) {
    asm volatile("cp.async.cg.shared.global [%0], [%1], 16;" :: "r"(dst), "l"(src) : "memory");
}
__device__ __forceinline__ void cp_commit() { asm volatile("cp.async.commit_group;" ::: "memory"); }
template <int N> __device__ __forceinline__ void cp_wait() {
    asm volatile("cp.async.wait_group %0;" :: "n"(N) : "memory");
}
__device__ __forceinline__ void ldsm4(uint32_t* r, uint32_t addr) {
    asm volatile("ldmatrix.sync.aligned.m8n8.x4.shared.b16 {%0,%1,%2,%3}, [%4];"
                 : "=r"(r[0]), "=r"(r[1]), "=r"(r[2]), "=r"(r[3]) : "r"(addr));
}
__device__ __forceinline__ void mma16816(float* c, const uint32_t* a, uint32_t b0, uint32_t b1) {
    asm volatile("mma.sync.aligned.m16n8k16.row.col.f32.f16.f16.f32 "
                 "{%0,%1,%2,%3}, {%4,%5,%6,%7}, {%8,%9}, {%0,%1,%2,%3};"
                 : "+f"(c[0]), "+f"(c[1]), "+f"(c[2]), "+f"(c[3])
                 : "r"(a[0]), "r"(a[1]), "r"(a[2]), "r"(a[3]), "r"(b0), "r"(b1));
}

// ---------------- kernel 0: zero the pooled-mean buffer ---------------------
__global__ void k_zero() {
    int i = blockIdx.x * blockDim.x + threadIdx.x;
    if (i < BSZ*DSZ) g_xmean[i] = 0.f;
}

// ---------------- kernel 1a: parallel mean pool (grid B x 16) ---------------
__global__ __launch_bounds__(256) void k_pool(const float* __restrict__ x) {
    int b = blockIdx.x;
    int s0 = blockIdx.y * (SSZ/16);
    const float inv = 1.0f / SSZ;
    float acc[4][4] = {};
    const float* xb = x + (size_t)b*SSZ*DSZ;
    for (int s = s0; s < s0 + SSZ/16; s++) {
        const float* row = xb + (size_t)s*DSZ;
#pragma unroll
        for (int g = 0; g < 4; g++) {
            float4 v = *(const float4*)(row + g*1024 + threadIdx.x*4);
            acc[g][0] += v.x; acc[g][1] += v.y; acc[g][2] += v.z; acc[g][3] += v.w;
        }
    }
#pragma unroll
    for (int g = 0; g < 4; g++)
#pragma unroll
        for (int j = 0; j < 4; j++)
            atomicAdd(&g_xmean[b*DSZ + g*1024 + threadIdx.x*4 + j], acc[g][j] * inv);
}

// ---------------- kernel 1b: router logits + softmax (1 block) --------------
__global__ __launch_bounds__(256) void k_logits(const float* __restrict__ rW,
                                                const float* __restrict__ rb) {
    __shared__ float lg[BSZ][ESZ];
    int tid = threadIdx.x;
    if (tid < BSZ*ESZ) ((float*)lg)[tid] = 0.f;
    __syncthreads();
    for (int be = 0; be < BSZ*ESZ; be++) {
        int b = be >> 3, e = be & 7;
        float p = 0.f;
        for (int d = tid; d < DSZ; d += 256) p += g_xmean[b*DSZ + d] * rW[(size_t)e*DSZ + d];
        for (int o = 16; o; o >>= 1) p += __shfl_xor_sync(0xffffffffu, p, o);
        if ((tid & 31) == 0) atomicAdd(&lg[b][e], p);
    }
    __syncthreads();
    if (tid < BSZ) {
        int b = tid;
        float l[ESZ], mx = -1e30f;
        for (int e = 0; e < ESZ; e++) { l[e] = lg[b][e] + rb[e]; mx = fmaxf(mx, l[e]); }
        float sum = 0.f;
        for (int e = 0; e < ESZ; e++) { l[e] = expf(l[e] - mx); sum += l[e]; }
        for (int e = 0; e < ESZ; e++) g_weights[b*ESZ + e] = l[e] / sum;
    }
}

// ---------------- kernel 2: B' = [W_base | SCALING*B_cat] -> fp16 -----------
__global__ __launch_bounds__(256) void k_cvtB(const float* __restrict__ W,
                                              const float* __restrict__ lB) {
    int o = blockIdx.x;
    for (int c4 = threadIdx.x; c4 < DSZ/4; c4 += 256) {
        float4 v = *(const float4*)(W + (size_t)o*DSZ + c4*4);
        size_t off = (size_t)o*KTOT + c4*4;
        g_Bh[off+0] = __float2half(v.x); g_Bh[off+1] = __float2half(v.y);
        g_Bh[off+2] = __float2half(v.z); g_Bh[off+3] = __float2half(v.w);
    }
    if (threadIdx.x < KLORA) {
        int k = threadIdx.x;
        int e = k >> 3, r = k & 7;
        float v = SCALING * lB[((size_t)e*OSZ + o)*RSZ + r];
        g_Bh[(size_t)o*KTOT + DSZ + k] = __float2half(v);
    }
}

// ---------------- kernel 3: x -> fp16 into A' cols [0,4096) -----------------
__global__ __launch_bounds__(256) void k_cvtX(const float* __restrict__ x) {
    int m = blockIdx.x;
    for (int c4 = threadIdx.x; c4 < DSZ/4; c4 += 256) {
        float4 v = *(const float4*)(x + (size_t)m*DSZ + c4*4);
        size_t off = (size_t)m*KTOT + c4*4;
        g_Ah[off+0] = __float2half(v.x); g_Ah[off+1] = __float2half(v.y);
        g_Ah[off+2] = __float2half(v.z); g_Ah[off+3] = __float2half(v.w);
    }
}

// ---------------- kernel 4: h = x@A_cat^T, router-weight -> fp16 ------------
__global__ __launch_bounds__(256) void k_h(const float* __restrict__ x,
                                           const float* __restrict__ lA) {
    __shared__ float xs[32][65];
    __shared__ float as[64][65];
    int tid = threadIdx.x;
    int m0 = blockIdx.x * 32;
    int ty = tid >> 4, tx = tid & 15;
    float acc[2][4] = {};
    for (int kt = 0; kt < DSZ; kt += 64) {
        __syncthreads();
#pragma unroll
        for (int i = 0; i < 2; i++) {
            int q = tid + i*256;
            int r = q >> 4, c4 = q & 15;
            float4 v = *(const float4*)(x + (size_t)(m0 + r)*DSZ + kt + c4*4);
            xs[r][c4*4+0] = v.x; xs[r][c4*4+1] = v.y; xs[r][c4*4+2] = v.z; xs[r][c4*4+3] = v.w;
        }
#pragma unroll
        for (int i = 0; i < 4; i++) {
            int q = tid + i*256;
            int r = q >> 4, c4 = q & 15;
            float4 v = *(const float4*)(lA + (size_t)r*DSZ + kt + c4*4);
            as[r][c4*4+0] = v.x; as[r][c4*4+1] = v.y; as[r][c4*4+2] = v.z; as[r][c4*4+3] = v.w;
        }
        __syncthreads();
#pragma unroll 8
        for (int kk = 0; kk < 64; kk++) {
            float xv[2], av[4];
            xv[0] = xs[ty*2 + 0][kk];
            xv[1] = xs[ty*2 + 1][kk];
#pragma unroll
            for (int j = 0; j < 4; j++) av[j] = as[tx*4 + j][kk];
#pragma unroll
            for (int i = 0; i < 2; i++)
#pragma unroll
                for (int j = 0; j < 4; j++) acc[i][j] += xv[i]*av[j];
        }
    }
#pragma unroll
    for (int i = 0; i < 2; i++) {
        int m = m0 + ty*2 + i;
        int b = m >> 11;
#pragma unroll
        for (int j = 0; j < 4; j++) {
            int c = tx*4 + j;
            float v = acc[i][j] * g_weights[b*ESZ + (c >> 3)];
            g_Ah[(size_t)m*KTOT + DSZ + c] = __float2half(v);
        }
    }
}

// ---------------- kernel 5: main GEMM, fp16, 128x256 tile, 3-stage ----------
// CTA tile 128Mx256N, warp tile 64x64 (2x4 warps), KC=64, 3-stage cp.async.
// Rows are 128B (64 fp16), 8x16B chunks, XOR swizzle pc = c ^ (r&7).
#define KC2   64
#define NKT2  (KTOT/KC2)         // 65
#define TA    (128*64*2)         // 16384  A stage tile
#define TB    (256*64*2)         // 32768  B stage tile
#define STAGEB (TA + TB)         // 49152
#define GEMM_SMEM (3*STAGEB)     // 147456

__global__ __launch_bounds__(256, 1) void k_gemm(const float* __restrict__ bias,
                                                 float* __restrict__ out) {
    extern __shared__ char smem[];
    const uint32_t sb = s2u(smem);
    const int tid = threadIdx.x;
    const int m0 = blockIdx.y * 128;
    const int n0 = blockIdx.x * 256;
    const int w = tid >> 5, l = tid & 31;
    const int mw = (w & 1) * 64;       // 2 warps in M
    const int nw = (w >> 1) * 64;      // 4 warps in N

    // ldmatrix lane mappings (verified R6/R7)
    const int rA = l & 15, halfA = l >> 4;
    const int rB = ((l >> 4) & 1) * 8 + (l & 7);
    const int halfB = (l >> 3) & 1;

    const __half* srcA = g_Ah + (size_t)m0*KTOT;
    const __half* srcB = g_Bh + (size_t)n0*KTOT;

    float acc[4][8][4];
#pragma unroll
    for (int a = 0; a < 4; a++)
#pragma unroll
        for (int b = 0; b < 8; b++)
#pragma unroll
            for (int c = 0; c < 4; c++) acc[a][b][c] = 0.f;

    // load chunk `ck` into stage `st`
    auto load_chunk = [&](int st, int ck) {
        uint32_t base = sb + st * STAGEB;
        int k0 = ck * KC2;
#pragma unroll
        for (int i = 0; i < 4; i++) {      // A: 1024 cp16
            int u = tid + i*256;
            int r = u >> 3, c = u & 7, pc = c ^ (r & 7);
            cp16(base + r*128 + pc*16, srcA + (size_t)r*KTOT + k0 + c*8);
        }
#pragma unroll
        for (int i = 0; i < 8; i++) {      // B: 2048 cp16
            int u = tid + i*256;
            int r = u >> 3, c = u & 7, pc = c ^ (r & 7);
            cp16(base + TA + r*128 + pc*16, srcB + (size_t)r*KTOT + k0 + c*8);
        }
        cp_commit();
    };

    // prologue: chunks 0,1 into stages 0,1
    load_chunk(0, 0);
    load_chunk(1, 1);

    for (int kt = 0; kt < NKT2; kt++) {
        int s = kt % 3;
        if (kt + 1 < NKT2) cp_wait<1>(); else cp_wait<0>();
        __syncthreads();
        if (kt + 2 < NKT2) load_chunk((kt + 2) % 3, kt + 2);

        uint32_t At = sb + s*STAGEB;
        uint32_t Bt = At + TA;

#pragma unroll
        for (int ks = 0; ks < 4; ks++) {
            uint32_t a[4][4], b[4][4];
#pragma unroll
            for (int mt = 0; mt < 4; mt++) {
                int r = mw + mt*16 + rA;
                uint32_t off = (uint32_t)(r*128 + (((2*ks + halfA) ^ (r & 7)) * 16));
                ldsm4(a[mt], At + off);
            }
#pragma unroll
            for (int np = 0; np < 4; np++) {
                int r = nw + np*16 + rB;
                uint32_t off = (uint32_t)(r*128 + (((2*ks + halfB) ^ (r & 7)) * 16));
                ldsm4(b[np], Bt + off);
            }
#pragma unroll
            for (int mt = 0; mt < 4; mt++)
#pragma unroll
                for (int nt = 0; nt < 8; nt++) {
                    int np = nt >> 1, h = (nt & 1) * 2;
                    mma16816(acc[mt][nt], a[mt], b[np][h], b[np][h+1]);
                }
        }
    }

    // epilogue: add bias, store fp32
#pragma unroll
    for (int mt = 0; mt < 4; mt++) {
        int row = m0 + mw + mt*16 + (l >> 2);
#pragma unroll
        for (int nt = 0; nt < 8; nt++) {
            int col = n0 + nw + nt*8 + (l & 3)*2;
            float b0 = bias[col], b1 = bias[col+1];
            float* p0 = out + (size_t)row*OSZ + col;
            float* p1 = out + (size_t)(row + 8)*OSZ + col;
            float2 v0 = { acc[mt][nt][0] + b0, acc[mt][nt][1] + b1 };
            float2 v1 = { acc[mt][nt][2] + b0, acc[mt][nt][3] + b1 };
            *(float2*)p0 = v0;
            *(float2*)p1 = v1;
        }
    }
}

// ---------------- launch ----------------
extern "C" void kernel_launch(void* const* d_in, const int* in_sizes, int n_in,
                              void* d_out, int out_size) {
    const float* x  = (const float*)d_in[0];
    const float* Wb = (const float*)d_in[1];
    const float* bb = (const float*)d_in[2];
    const float* lA = (const float*)d_in[3];
    const float* lB = (const float*)d_in[4];
    const float* rW = (const float*)d_in[5];
    const float* rb = (const float*)d_in[6];
    float* out = (float*)d_out;

    cudaFuncSetAttribute((const void*)k_gemm,
                         cudaFuncAttributeMaxDynamicSharedMemorySize, GEMM_SMEM);

    k_zero<<<(BSZ*DSZ + 255)/256, 256>>>();
    k_pool<<<dim3(BSZ, 16), 256>>>(x);
    k_logits<<<1, 256>>>(rW, rb);
    k_cvtB<<<OSZ, 256>>>(Wb, lB);
    k_cvtX<<<MSZ, 256>>>(x);
    k_h<<<MSZ/32, 256>>>(x, lA);
    k_gemm<<<dim3(OSZ/256, MSZ/128), 256, GEMM_SMEM>>>(bb, out);
}

// round 10
// speedup vs baseline: 1.2377x; 1.2377x over previous
#include <cuda_runtime.h>
#include <cuda_fp16.h>
#include <cstdint>
#include <cstddef>

#define BSZ 4
#define SSZ 2048
#define DSZ 4096
#define OSZ 4096
#define ESZ 8
#define RSZ 8
#define MSZ (BSZ*SSZ)            // 8192
#define KLORA (ESZ*RSZ)          // 64
#define KTOT (DSZ+KLORA)         // 4160
#define SCALING 2.0f             // lora_alpha / r = 16/8

// ---------------- scratch (device globals; allocation is forbidden) ----------
__device__ __align__(128) __half g_Ah[(size_t)MSZ*KTOT];   // [x | h(unweighted)] fp16
__device__ __align__(128) __half g_Bh[(size_t)OSZ*KTOT];   // [W | 2*B_cat] fp16
__device__ float g_xmean[BSZ*DSZ];
__device__ float g_weights[BSZ*ESZ];

// ---------------- PTX helpers (compute_80-era; sm_103 virtual-arch safe) ----
__device__ __forceinline__ uint32_t s2u(const void* p) {
    uint32_t a;
    asm("{ .reg .u64 t; cvta.to.shared.u64 t, %1; cvt.u32.u64 %0, t; }" : "=r"(a) : "l"(p));
    return a;
}
__device__ __forceinline__ void cp16(uint32_t dst, const void* src) {
    asm volatile("cp.async.cg.shared.global [%0], [%1], 16;" :: "r"(dst), "l"(src) : "memory");
}
__device__ __forceinline__ void cp_commit() { asm volatile("cp.async.commit_group;" ::: "memory"); }
template <int N> __device__ __forceinline__ void cp_wait() {
    asm volatile("cp.async.wait_group %0;" :: "n"(N) : "memory");
}
__device__ __forceinline__ void ldsm4(uint32_t* r, uint32_t addr) {
    asm volatile("ldmatrix.sync.aligned.m8n8.x4.shared.b16 {%0,%1,%2,%3}, [%4];"
                 : "=r"(r[0]), "=r"(r[1]), "=r"(r[2]), "=r"(r[3]) : "r"(addr));
}
__device__ __forceinline__ void mma16816(float* c, const uint32_t* a, uint32_t b0, uint32_t b1) {
    asm volatile("mma.sync.aligned.m16n8k16.row.col.f32.f16.f16.f32 "
                 "{%0,%1,%2,%3}, {%4,%5,%6,%7}, {%8,%9}, {%0,%1,%2,%3};"
                 : "+f"(c[0]), "+f"(c[1]), "+f"(c[2]), "+f"(c[3])
                 : "r"(a[0]), "r"(a[1]), "r"(a[2]), "r"(a[3]), "r"(b0), "r"(b1));
}

// ---------------- kernel 0: zero the pooled-mean buffer ---------------------
__global__ void k_zero() {
    int i = blockIdx.x * blockDim.x + threadIdx.x;
    if (i < BSZ*DSZ) g_xmean[i] = 0.f;
}

// ---------------- kernel 1: FUSED single pass over x ------------------------
// Per CTA: 32 rows of x. Does (a) fp16 convert of x into A' cols [0,4096),
// (b) mean-pool partial sums (atomicAdd), (c) h = x @ lora_A^T (UNWEIGHTED)
// into A' cols [4096,4160). Router weights are applied later inside the GEMM.
__global__ __launch_bounds__(256) void k_prep(const float* __restrict__ x,
                                              const float* __restrict__ lA) {
    __shared__ float xs[32][65];
    __shared__ float as[64][65];
    int tid = threadIdx.x;
    int m0 = blockIdx.x * 32;
    int b = m0 >> 11;
    int ty = tid >> 4, tx = tid & 15;
    const float inv = 1.0f / SSZ;
    float acc[2][4] = {};
    for (int kt = 0; kt < DSZ; kt += 64) {
        __syncthreads();
        // xs tile 32x64 (2 float4 per thread), also emit fp16 x
#pragma unroll
        for (int i = 0; i < 2; i++) {
            int q = tid + i*256;
            int r = q >> 4, c4 = q & 15;
            float4 v = *(const float4*)(x + (size_t)(m0 + r)*DSZ + kt + c4*4);
            xs[r][c4*4+0] = v.x; xs[r][c4*4+1] = v.y; xs[r][c4*4+2] = v.z; xs[r][c4*4+3] = v.w;
            __half2* dst = (__half2*)(g_Ah + (size_t)(m0 + r)*KTOT + kt + c4*4);
            dst[0] = __floats2half2_rn(v.x, v.y);
            dst[1] = __floats2half2_rn(v.z, v.w);
        }
        // as tile 64x64 (4 float4 per thread)  — lora_A viewed [64,4096]
#pragma unroll
        for (int i = 0; i < 4; i++) {
            int q = tid + i*256;
            int r = q >> 4, c4 = q & 15;
            float4 v = *(const float4*)(lA + (size_t)r*DSZ + kt + c4*4);
            as[r][c4*4+0] = v.x; as[r][c4*4+1] = v.y; as[r][c4*4+2] = v.z; as[r][c4*4+3] = v.w;
        }
        __syncthreads();
        // pooling: threads 0..63 each sum one column over the 32 rows
        if (tid < 64) {
            float s = 0.f;
#pragma unroll 8
            for (int r = 0; r < 32; r++) s += xs[r][tid];
            atomicAdd(&g_xmean[b*DSZ + kt + tid], s * inv);
        }
        // h accumulation
#pragma unroll 8
        for (int kk = 0; kk < 64; kk++) {
            float xv[2], av[4];
            xv[0] = xs[ty*2 + 0][kk];
            xv[1] = xs[ty*2 + 1][kk];
#pragma unroll
            for (int j = 0; j < 4; j++) av[j] = as[tx*4 + j][kk];
#pragma unroll
            for (int i = 0; i < 2; i++)
#pragma unroll
                for (int j = 0; j < 4; j++) acc[i][j] += xv[i]*av[j];
        }
    }
#pragma unroll
    for (int i = 0; i < 2; i++) {
        int m = m0 + ty*2 + i;
#pragma unroll
        for (int j = 0; j < 4; j++) {
            int c = tx*4 + j;
            g_Ah[(size_t)m*KTOT + DSZ + c] = __float2half(acc[i][j]);   // unweighted
        }
    }
}

// ---------------- kernel 2: router logits + softmax (1 block) --------------
__global__ __launch_bounds__(256) void k_logits(const float* __restrict__ rW,
                                                const float* __restrict__ rb) {
    __shared__ float lg[BSZ][ESZ];
    int tid = threadIdx.x;
    if (tid < BSZ*ESZ) ((float*)lg)[tid] = 0.f;
    __syncthreads();
    for (int be = 0; be < BSZ*ESZ; be++) {
        int b = be >> 3, e = be & 7;
        float p = 0.f;
        for (int d = tid; d < DSZ; d += 256) p += g_xmean[b*DSZ + d] * rW[(size_t)e*DSZ + d];
        for (int o = 16; o; o >>= 1) p += __shfl_xor_sync(0xffffffffu, p, o);
        if ((tid & 31) == 0) atomicAdd(&lg[b][e], p);
    }
    __syncthreads();
    if (tid < BSZ) {
        int b = tid;
        float l[ESZ], mx = -1e30f;
        for (int e = 0; e < ESZ; e++) { l[e] = lg[b][e] + rb[e]; mx = fmaxf(mx, l[e]); }
        float sum = 0.f;
        for (int e = 0; e < ESZ; e++) { l[e] = expf(l[e] - mx); sum += l[e]; }
        for (int e = 0; e < ESZ; e++) g_weights[b*ESZ + e] = l[e] / sum;
    }
}

// ---------------- kernel 3: B' = [W_base | SCALING*B_cat] -> fp16 -----------
__global__ __launch_bounds__(256) void k_cvtB(const float* __restrict__ W,
                                              const float* __restrict__ lB) {
    int o = blockIdx.x;
    for (int c4 = threadIdx.x; c4 < DSZ/4; c4 += 256) {
        float4 v = *(const float4*)(W + (size_t)o*DSZ + c4*4);
        __half2* dst = (__half2*)(g_Bh + (size_t)o*KTOT + c4*4);
        dst[0] = __floats2half2_rn(v.x, v.y);
        dst[1] = __floats2half2_rn(v.z, v.w);
    }
    if (threadIdx.x < KLORA) {
        int k = threadIdx.x;
        int e = k >> 3, r = k & 7;
        float v = SCALING * lB[((size_t)e*OSZ + o)*RSZ + r];
        g_Bh[(size_t)o*KTOT + DSZ + k] = __float2half(v);
    }
}

// ---------------- kernel 4: main GEMM, fp16, 128x128, 3-stage ---------------
// R7-proven 64x32 warp tiles, 2 CTAs/SM. 3-stage cp.async ring, ONE sync per
// chunk. Router weights applied to the B tile's LoRA chunk (kt==64) in smem.
#define KC2   64
#define NKT2  (KTOT/KC2)         // 65
#define TILEB (128*64*2)         // 16384
#define STAGEB (2*TILEB)         // 32768 (A + B)
#define GEMM_SMEM (3*STAGEB)     // 98304

__global__ __launch_bounds__(256, 2) void k_gemm(const float* __restrict__ bias,
                                                 float* __restrict__ out) {
    extern __shared__ char smem[];
    const uint32_t sb = s2u(smem);
    const int tid = threadIdx.x;
    const int m0 = blockIdx.y * 128;
    const int n0 = blockIdx.x * 128;
    const int w = tid >> 5, l = tid & 31;
    const int mw = (w & 1) * 64;       // 2 warps in M
    const int nw = (w >> 1) * 32;      // 4 warps in N
    const int bidx = m0 >> 11;         // batch of this CTA

    const int rA = l & 15, halfA = l >> 4;
    const int rB = ((l >> 4) & 1) * 8 + (l & 7);
    const int halfB = (l >> 3) & 1;

    const __half* srcA = g_Ah + (size_t)m0*KTOT;
    const __half* srcB = g_Bh + (size_t)n0*KTOT;

    float acc[4][4][4];
#pragma unroll
    for (int a = 0; a < 4; a++)
#pragma unroll
        for (int b = 0; b < 4; b++)
#pragma unroll
            for (int c = 0; c < 4; c++) acc[a][b][c] = 0.f;

    auto load_chunk = [&](int st, int ck) {
        uint32_t base = sb + st * STAGEB;
        int k0 = ck * KC2;
#pragma unroll
        for (int i = 0; i < 4; i++) {
            int u = tid + i*256;
            int r = u >> 3, c = u & 7, pc = c ^ (r & 7);
            cp16(base + r*128 + pc*16, srcA + (size_t)r*KTOT + k0 + c*8);
            cp16(base + TILEB + r*128 + pc*16, srcB + (size_t)r*KTOT + k0 + c*8);
        }
        cp_commit();
    };

    load_chunk(0, 0);
    load_chunk(1, 1);

    for (int kt = 0; kt < NKT2; kt++) {
        int s = kt % 3;
        if (kt + 1 < NKT2) cp_wait<1>(); else cp_wait<0>();
        __syncthreads();
        if (kt + 2 < NKT2) load_chunk((kt + 2) % 3, kt + 2);

        uint32_t At = sb + s*STAGEB;
        uint32_t Bt = At + TILEB;

        if (kt == NKT2 - 1) {
            // scale B LoRA columns by router weight; each 16B smem chunk is
            // one expert: k = c*8..c*8+7  ->  e = c
#pragma unroll
            for (int i = 0; i < 4; i++) {
                int u = tid + i*256;
                int r = u >> 3, c = u & 7, pc = c ^ (r & 7);
                __half2 w2 = __float2half2_rn(g_weights[bidx*ESZ + c]);
                __half2* p = (__half2*)(smem + (Bt - sb) + r*128 + pc*16);
                p[0] = __hmul2(p[0], w2);
                p[1] = __hmul2(p[1], w2);
                p[2] = __hmul2(p[2], w2);
                p[3] = __hmul2(p[3], w2);
            }
            __syncthreads();
        }

#pragma unroll
        for (int ks = 0; ks < 4; ks++) {
            uint32_t a[4][4], b[2][4];
#pragma unroll
            for (int mt = 0; mt < 4; mt++) {
                int r = mw + mt*16 + rA;
                uint32_t off = (uint32_t)(r*128 + (((2*ks + halfA) ^ (r & 7)) * 16));
                ldsm4(a[mt], At + off);
            }
#pragma unroll
            for (int np = 0; np < 2; np++) {
                int r = nw + np*16 + rB;
                uint32_t off = (uint32_t)(r*128 + (((2*ks + halfB) ^ (r & 7)) * 16));
                ldsm4(b[np], Bt + off);
            }
#pragma unroll
            for (int mt = 0; mt < 4; mt++)
#pragma unroll
                for (int nt = 0; nt < 4; nt++) {
                    int np = nt >> 1, h = (nt & 1) * 2;
                    mma16816(acc[mt][nt], a[mt], b[np][h], b[np][h+1]);
                }
        }
    }

    // epilogue: add bias, store fp32
#pragma unroll
    for (int mt = 0; mt < 4; mt++) {
        int row = m0 + mw + mt*16 + (l >> 2);
#pragma unroll
        for (int nt = 0; nt < 4; nt++) {
            int col = n0 + nw + nt*8 + (l & 3)*2;
            float b0 = bias[col], b1 = bias[col+1];
            float* p0 = out + (size_t)row*OSZ + col;
            float* p1 = out + (size_t)(row + 8)*OSZ + col;
            float2 v0 = { acc[mt][nt][0] + b0, acc[mt][nt][1] + b1 };
            float2 v1 = { acc[mt][nt][2] + b0, acc[mt][nt][3] + b1 };
            *(float2*)p0 = v0;
            *(float2*)p1 = v1;
        }
    }
}

// ---------------- launch ----------------
extern "C" void kernel_launch(void* const* d_in, const int* in_sizes, int n_in,
                              void* d_out, int out_size) {
    const float* x  = (const float*)d_in[0];
    const float* Wb = (const float*)d_in[1];
    const float* bb = (const float*)d_in[2];
    const float* lA = (const float*)d_in[3];
    const float* lB = (const float*)d_in[4];
    const float* rW = (const float*)d_in[5];
    const float* rb = (const float*)d_in[6];
    float* out = (float*)d_out;

    cudaFuncSetAttribute((const void*)k_gemm,
                         cudaFuncAttributeMaxDynamicSharedMemorySize, GEMM_SMEM);

    k_zero<<<(BSZ*DSZ + 255)/256, 256>>>();
    k_prep<<<MSZ/32, 256>>>(x, lA);
    k_logits<<<1, 256>>>(rW, rb);
    k_cvtB<<<OSZ, 256>>>(Wb, lB);
    k_gemm<<<dim3(OSZ/128, MSZ/128), 256, GEMM_SMEM>>>(bb, out);
}

// round 12
// speedup vs baseline: 1.9301x; 1.5594x over previous
#include <cuda_runtime.h>
#include <cuda_fp16.h>
#include <cstdint>
#include <cstddef>

#define BSZ 4
#define SSZ 2048
#define DSZ 4096
#define OSZ 4096
#define ESZ 8
#define RSZ 8
#define MSZ (BSZ*SSZ)            // 8192
#define KLORA (ESZ*RSZ)          // 64
#define KTOT (DSZ+KLORA)         // 4160
#define SCALING 2.0f             // lora_alpha / r = 16/8

// ---------------- scratch (device globals; allocation is forbidden) ----------
__device__ __align__(128) __half g_Ah[(size_t)MSZ*KTOT];   // [x | h(unweighted)] fp16
__device__ __align__(128) __half g_Bh[(size_t)OSZ*KTOT];   // [W | 2*B_cat] fp16
__device__ float g_xmean[BSZ*DSZ];
__device__ float g_weights[BSZ*ESZ];

// ---------------- PTX helpers (compute_80-era; sm_103 virtual-arch safe) ----
__device__ __forceinline__ uint32_t s2u(const void* p) {
    uint32_t a;
    asm("{ .reg .u64 t; cvta.to.shared.u64 t, %1; cvt.u32.u64 %0, t; }" : "=r"(a) : "l"(p));
    return a;
}
__device__ __forceinline__ void cp16(uint32_t dst, const void* src) {
    asm volatile("cp.async.cg.shared.global [%0], [%1], 16;" :: "r"(dst), "l"(src) : "memory");
}
__device__ __forceinline__ void cp_commit() { asm volatile("cp.async.commit_group;" ::: "memory"); }
template <int N> __device__ __forceinline__ void cp_wait() {
    asm volatile("cp.async.wait_group %0;" :: "n"(N) : "memory");
}
__device__ __forceinline__ void ldsm4(uint32_t* r, uint32_t addr) {
    asm volatile("ldmatrix.sync.aligned.m8n8.x4.shared.b16 {%0,%1,%2,%3}, [%4];"
                 : "=r"(r[0]), "=r"(r[1]), "=r"(r[2]), "=r"(r[3]) : "r"(addr));
}
__device__ __forceinline__ void mma16816(float* c, const uint32_t* a, uint32_t b0, uint32_t b1) {
    asm volatile("mma.sync.aligned.m16n8k16.row.col.f32.f16.f16.f32 "
                 "{%0,%1,%2,%3}, {%4,%5,%6,%7}, {%8,%9}, {%0,%1,%2,%3};"
                 : "+f"(c[0]), "+f"(c[1]), "+f"(c[2]), "+f"(c[3])
                 : "r"(a[0]), "r"(a[1]), "r"(a[2]), "r"(a[3]), "r"(b0), "r"(b1));
}

// ---------------- kernel 0: zero the pooled-mean buffer ---------------------
__global__ void k_zero() {
    int i = blockIdx.x * blockDim.x + threadIdx.x;
    if (i < BSZ*DSZ) g_xmean[i] = 0.f;
}

// ---------------- kernel 1: FUSED single pass over x ------------------------
// Per CTA: 32 rows of x. (a) fp16 convert of x into A' cols [0,4096),
// (b) mean-pool partial sums (atomicAdd), (c) h = x @ lora_A^T (UNWEIGHTED)
// into A' cols [4096,4160). Router weights get applied inside the GEMM.
__global__ __launch_bounds__(256) void k_prep(const float* __restrict__ x,
                                              const float* __restrict__ lA) {
    __shared__ float xs[32][65];
    __shared__ float as[64][65];
    int tid = threadIdx.x;
    int m0 = blockIdx.x * 32;
    int b = m0 >> 11;
    int ty = tid >> 4, tx = tid & 15;
    const float inv = 1.0f / SSZ;
    float acc[2][4] = {};
    for (int kt = 0; kt < DSZ; kt += 64) {
        __syncthreads();
#pragma unroll
        for (int i = 0; i < 2; i++) {
            int q = tid + i*256;
            int r = q >> 4, c4 = q & 15;
            float4 v = *(const float4*)(x + (size_t)(m0 + r)*DSZ + kt + c4*4);
            xs[r][c4*4+0] = v.x; xs[r][c4*4+1] = v.y; xs[r][c4*4+2] = v.z; xs[r][c4*4+3] = v.w;
            __half2* dst = (__half2*)(g_Ah + (size_t)(m0 + r)*KTOT + kt + c4*4);
            dst[0] = __floats2half2_rn(v.x, v.y);
            dst[1] = __floats2half2_rn(v.z, v.w);
        }
#pragma unroll
        for (int i = 0; i < 4; i++) {
            int q = tid + i*256;
            int r = q >> 4, c4 = q & 15;
            float4 v = *(const float4*)(lA + (size_t)r*DSZ + kt + c4*4);
            as[r][c4*4+0] = v.x; as[r][c4*4+1] = v.y; as[r][c4*4+2] = v.z; as[r][c4*4+3] = v.w;
        }
        __syncthreads();
        if (tid < 64) {
            float s = 0.f;
#pragma unroll 8
            for (int r = 0; r < 32; r++) s += xs[r][tid];
            atomicAdd(&g_xmean[b*DSZ + kt + tid], s * inv);
        }
#pragma unroll 8
        for (int kk = 0; kk < 64; kk++) {
            float xv[2], av[4];
            xv[0] = xs[ty*2 + 0][kk];
            xv[1] = xs[ty*2 + 1][kk];
#pragma unroll
            for (int j = 0; j < 4; j++) av[j] = as[tx*4 + j][kk];
#pragma unroll
            for (int i = 0; i < 2; i++)
#pragma unroll
                for (int j = 0; j < 4; j++) acc[i][j] += xv[i]*av[j];
        }
    }
#pragma unroll
    for (int i = 0; i < 2; i++) {
        int m = m0 + ty*2 + i;
#pragma unroll
        for (int j = 0; j < 4; j++) {
            int c = tx*4 + j;
            g_Ah[(size_t)m*KTOT + DSZ + c] = __float2half(acc[i][j]);   // unweighted
        }
    }
}

// ---------------- kernel 2: router logits + softmax (1 block) --------------
__global__ __launch_bounds__(256) void k_logits(const float* __restrict__ rW,
                                                const float* __restrict__ rb) {
    __shared__ float lg[BSZ][ESZ];
    int tid = threadIdx.x;
    if (tid < BSZ*ESZ) ((float*)lg)[tid] = 0.f;
    __syncthreads();
    for (int be = 0; be < BSZ*ESZ; be++) {
        int b = be >> 3, e = be & 7;
        float p = 0.f;
        for (int d = tid; d < DSZ; d += 256) p += g_xmean[b*DSZ + d] * rW[(size_t)e*DSZ + d];
        for (int o = 16; o; o >>= 1) p += __shfl_xor_sync(0xffffffffu, p, o);
        if ((tid & 31) == 0) atomicAdd(&lg[b][e], p);
    }
    __syncthreads();
    if (tid < BSZ) {
        int b = tid;
        float l[ESZ], mx = -1e30f;
        for (int e = 0; e < ESZ; e++) { l[e] = lg[b][e] + rb[e]; mx = fmaxf(mx, l[e]); }
        float sum = 0.f;
        for (int e = 0; e < ESZ; e++) { l[e] = expf(l[e] - mx); sum += l[e]; }
        for (int e = 0; e < ESZ; e++) g_weights[b*ESZ + e] = l[e] / sum;
    }
}

// ---------------- kernel 3: B' = [W_base | SCALING*B_cat] -> fp16 -----------
__global__ __launch_bounds__(256) void k_cvtB(const float* __restrict__ W,
                                              const float* __restrict__ lB) {
    int o = blockIdx.x;
    for (int c4 = threadIdx.x; c4 < DSZ/4; c4 += 256) {
        float4 v = *(const float4*)(W + (size_t)o*DSZ + c4*4);
        __half2* dst = (__half2*)(g_Bh + (size_t)o*KTOT + c4*4);
        dst[0] = __floats2half2_rn(v.x, v.y);
        dst[1] = __floats2half2_rn(v.z, v.w);
    }
    if (threadIdx.x < KLORA) {
        int k = threadIdx.x;
        int e = k >> 3, r = k & 7;
        float v = SCALING * lB[((size_t)e*OSZ + o)*RSZ + r];
        g_Bh[(size_t)o*KTOT + DSZ + k] = __float2half(v);
    }
}

// ---------------- kernel 4: main GEMM (R7-proven shape) ---------------------
// 128x128 CTA tile, 64x32 warp tiles, KC=64, 2-stage cp.async, 64 KB smem,
// 2 CTAs/SM. Router weights applied to B tile's LoRA chunk (kt==64) in smem.
#define KC2   64
#define NKT2  (KTOT/KC2)         // 65
#define TILEB (128*64*2)         // 16384
#define STAGEB (2*TILEB)         // 32768 (A + B)
#define GEMM_SMEM (2*STAGEB)     // 65536

__global__ __launch_bounds__(256, 2) void k_gemm(const float* __restrict__ bias,
                                                 float* __restrict__ out) {
    extern __shared__ char smem[];
    const uint32_t sb = s2u(smem);
    const int tid = threadIdx.x;
    const int m0 = blockIdx.y * 128;
    const int n0 = blockIdx.x * 128;
    const int w = tid >> 5, l = tid & 31;
    const int mw = (w & 1) * 64;       // 2 warps in M
    const int nw = (w >> 1) * 32;      // 4 warps in N
    const int bidx = m0 >> 11;         // batch of this CTA

    const int rA = l & 15, halfA = l >> 4;
    const int rB = ((l >> 4) & 1) * 8 + (l & 7);
    const int halfB = (l >> 3) & 1;

    const __half* srcA = g_Ah + (size_t)m0*KTOT;
    const __half* srcB = g_Bh + (size_t)n0*KTOT;

    float acc[4][4][4];
#pragma unroll
    for (int a = 0; a < 4; a++)
#pragma unroll
        for (int b = 0; b < 4; b++)
#pragma unroll
            for (int c = 0; c < 4; c++) acc[a][b][c] = 0.f;

    // prologue: stage 0 <- chunk 0
    {
#pragma unroll
        for (int i = 0; i < 4; i++) {
            int u = tid + i*256;
            int r = u >> 3, c = u & 7, pc = c ^ (r & 7);
            cp16(sb + r*128 + pc*16, srcA + (size_t)r*KTOT + c*8);
            cp16(sb + TILEB + r*128 + pc*16, srcB + (size_t)r*KTOT + c*8);
        }
        cp_commit();
    }

    for (int kt = 0; kt < NKT2; kt++) {
        int s = kt & 1;
        if (kt + 1 < NKT2) {
            uint32_t base = sb + (s ^ 1) * STAGEB;
            int k0 = (kt + 1) * KC2;
#pragma unroll
            for (int i = 0; i < 4; i++) {
                int u = tid + i*256;
                int r = u >> 3, c = u & 7, pc = c ^ (r & 7);
                cp16(base + r*128 + pc*16, srcA + (size_t)r*KTOT + k0 + c*8);
                cp16(base + TILEB + r*128 + pc*16, srcB + (size_t)r*KTOT + k0 + c*8);
            }
            cp_commit();
            cp_wait<1>();   // chunk kt's group complete
        } else {
            cp_wait<0>();
        }
        __syncthreads();

        uint32_t At = sb + s*STAGEB;
        uint32_t Bt = At + TILEB;

        if (kt == NKT2 - 1) {
            // scale B LoRA columns by router weight; each 16B smem chunk is
            // one expert: k = c*8..c*8+7 -> e = c
#pragma unroll
            for (int i = 0; i < 4; i++) {
                int u = tid + i*256;
                int r = u >> 3, c = u & 7, pc = c ^ (r & 7);
                __half2 w2 = __float2half2_rn(g_weights[bidx*ESZ + c]);
                __half2* p = (__half2*)(smem + (Bt - sb) + r*128 + pc*16);
                p[0] = __hmul2(p[0], w2);
                p[1] = __hmul2(p[1], w2);
                p[2] = __hmul2(p[2], w2);
                p[3] = __hmul2(p[3], w2);
            }
            __syncthreads();
        }

#pragma unroll
        for (int ks = 0; ks < 4; ks++) {
            uint32_t a[4][4], b[2][4];
#pragma unroll
            for (int mt = 0; mt < 4; mt++) {
                int r = mw + mt*16 + rA;
                uint32_t off = (uint32_t)(r*128 + (((2*ks + halfA) ^ (r & 7)) * 16));
                ldsm4(a[mt], At + off);
            }
#pragma unroll
            for (int np = 0; np < 2; np++) {
                int r = nw + np*16 + rB;
                uint32_t off = (uint32_t)(r*128 + (((2*ks + halfB) ^ (r & 7)) * 16));
                ldsm4(b[np], Bt + off);
            }
#pragma unroll
            for (int mt = 0; mt < 4; mt++)
#pragma unroll
                for (int nt = 0; nt < 4; nt++) {
                    int np = nt >> 1, h = (nt & 1) * 2;
                    mma16816(acc[mt][nt], a[mt], b[np][h], b[np][h+1]);
                }
        }
        __syncthreads();
    }

    // epilogue: add bias, store fp32
#pragma unroll
    for (int mt = 0; mt < 4; mt++) {
        int row = m0 + mw + mt*16 + (l >> 2);
#pragma unroll
        for (int nt = 0; nt < 4; nt++) {
            int col = n0 + nw + nt*8 + (l & 3)*2;
            float b0 = bias[col], b1 = bias[col+1];
            float* p0 = out + (size_t)row*OSZ + col;
            float* p1 = out + (size_t)(row + 8)*OSZ + col;
            float2 v0 = { acc[mt][nt][0] + b0, acc[mt][nt][1] + b1 };
            float2 v1 = { acc[mt][nt][2] + b0, acc[mt][nt][3] + b1 };
            *(float2*)p0 = v0;
            *(float2*)p1 = v1;
        }
    }
}

// ---------------- launch ----------------
extern "C" void kernel_launch(void* const* d_in, const int* in_sizes, int n_in,
                              void* d_out, int out_size) {
    const float* x  = (const float*)d_in[0];
    const float* Wb = (const float*)d_in[1];
    const float* bb = (const float*)d_in[2];
    const float* lA = (const float*)d_in[3];
    const float* lB = (const float*)d_in[4];
    const float* rW = (const float*)d_in[5];
    const float* rb = (const float*)d_in[6];
    float* out = (float*)d_out;

    cudaFuncSetAttribute((const void*)k_gemm,
                         cudaFuncAttributeMaxDynamicSharedMemorySize, GEMM_SMEM);

    k_zero<<<(BSZ*DSZ + 255)/256, 256>>>();
    k_prep<<<MSZ/32, 256>>>(x, lA);
    k_logits<<<1, 256>>>(rW, rb);
    k_cvtB<<<OSZ, 256>>>(Wb, lB);
    k_gemm<<<dim3(OSZ/128, MSZ/128), 256, GEMM_SMEM>>>(bb, out);
}